// round 17
// baseline (speedup 1.0000x reference)
#include <cuda_runtime.h>
#include <cuda_fp16.h>

#define NEDGES 3200000
#define NNODES 100000
#define HALF_EDGES (NEDGES / 2)                  // 1600000

// edge_stats launch geometry (compile-time so the loop is counted/predicate-free)
#define ES_BLOCKS 2500
#define ES_THREADS 256
#define NQUADS ((ES_BLOCKS * ES_THREADS) / 4)    // 160000 quads
#define ES_ITERS (HALF_EDGES / NQUADS)           // 10 exact; each iter does 2 edges

struct __align__(8) h4 { __half2 a, b; };                   // 4 halves = 8 B

// Scratch (static device allocation; no cudaMalloc anywhere)
static __device__ __align__(256) h4 g_h1[NNODES * 4];       // fp16 x@W1^T + bias (6.4 MB)
static __device__ __align__(256) h4 g_h2[NNODES * 4];       // fp16 x@W2^T        (6.4 MB)
static __device__ __align__(256) __half g_e[NEDGES * 16];   // fp16 pre-BN e (102.4 MB)
static __device__ float g_accum[32];                        // sum[16], sumsq[16]
static __device__ __align__(64) float g_scale[16];
static __device__ __align__(64) float g_shift[16];

// ============================================================================
// Kernel 1: per-node precompute h1 = fp16(x@W1^T + (b0+b1+b2)), h2 = fp16(x@W2^T).
// Also zeroes the stat accumulators (stream-ordered before edge_stats).
// ============================================================================
__global__ void node_prep(const float* __restrict__ x,
                          const float* __restrict__ W1,
                          const float* __restrict__ W2,
                          const float* __restrict__ b0,
                          const float* __restrict__ b1,
                          const float* __restrict__ b2) {
    __shared__ float W1t[256], W2t[256], bt[16];
    int tid = threadIdx.x;
    {
        int j = tid >> 4, k = tid & 15;          // W[j][k] at flat idx tid
        W1t[k * 16 + j] = W1[tid];               // transpose to [k][j]
        W2t[k * 16 + j] = W2[tid];
    }
    if (tid < 16) bt[tid] = b0[tid] + b1[tid] + b2[tid];
    __syncthreads();

    int n = blockIdx.x * blockDim.x + tid;
    if (n < NNODES) {
        const float4* xv = (const float4*)x + n * 4;
        float4 x0 = xv[0], x1 = xv[1], x2 = xv[2], x3 = xv[3];
        float xr[16] = {x0.x, x0.y, x0.z, x0.w, x1.x, x1.y, x1.z, x1.w,
                        x2.x, x2.y, x2.z, x2.w, x3.x, x3.y, x3.z, x3.w};
        float a1[16], a2[16];
        #pragma unroll
        for (int j = 0; j < 16; j++) { a1[j] = bt[j]; a2[j] = 0.f; }
        #pragma unroll
        for (int k = 0; k < 16; k++) {
            float xk = xr[k];
            #pragma unroll
            for (int j = 0; j < 16; j++) {
                a1[j] = fmaf(xk, W1t[k * 16 + j], a1[j]);
                a2[j] = fmaf(xk, W2t[k * 16 + j], a2[j]);
            }
        }
        #pragma unroll
        for (int qq = 0; qq < 4; qq++) {
            h4 v1, v2;
            v1.a = __floats2half2_rn(a1[4 * qq + 0], a1[4 * qq + 1]);
            v1.b = __floats2half2_rn(a1[4 * qq + 2], a1[4 * qq + 3]);
            v2.a = __floats2half2_rn(a2[4 * qq + 0], a2[4 * qq + 1]);
            v2.b = __floats2half2_rn(a2[4 * qq + 2], a2[4 * qq + 3]);
            g_h1[n * 4 + qq] = v1;
            g_h2[n * 4 + qq] = v2;
        }
    }
    if (blockIdx.x == 0 && tid < 32) g_accum[tid] = 0.f;
}

// ============================================================================
// Kernel 2: pass 1 — quad layout, ILP=2: each quad processes the edge pair
// (e, e+HALF_EDGES) per iteration — two independent FMA/load chains per body.
// 3-stage software pipeline: indices 2 iters ahead, data (ea + fp16 gathers)
// 1 iter ahead. Counted loop (10 iters exactly). W0 register-resident.
// ============================================================================
__global__ void __launch_bounds__(ES_THREADS, 2) edge_stats(const float* __restrict__ ea,
                                                            const int* __restrict__ ei,
                                                            const float* __restrict__ W0) {
    __shared__ float red[8][32];
    int tid = threadIdx.x;
    int q = tid & 3;
    int lane = tid & 31;
    int qbase = lane & 28;

    // w[i][g] = W0[4q+i][4g..4g+3]  (loop-invariant, register-resident)
    float4 w[4][4];
    #pragma unroll
    for (int i = 0; i < 4; i++)
        #pragma unroll
        for (int g = 0; g < 4; g++)
            w[i][g] = __ldg(&((const float4*)W0)[(4 * q + i) * 4 + g]);

    int qid = (blockIdx.x * blockDim.x + tid) >> 2;

    float S[4] = {0.f, 0.f, 0.f, 0.f};
    float Q[4] = {0.f, 0.f, 0.f, 0.f};
    const float4* eav = (const float4*)ea;
    float2* ev = (float2*)g_e;

    // ---- pipeline prologue ----
    int eA0 = qid;                               // edge A: [0, HALF_EDGES)
    int eA1 = eA0 + NQUADS;
    // indices for iter0 and iter1, both edges of each pair
    int sA0 = ei[eA0],              dA0 = ei[NEDGES + eA0];
    int sB0 = ei[eA0 + HALF_EDGES], dB0 = ei[NEDGES + eA0 + HALF_EDGES];
    int sA1 = ei[eA1],              dA1 = ei[NEDGES + eA1];
    int sB1 = ei[eA1 + HALF_EDGES], dB1 = ei[NEDGES + eA1 + HALF_EDGES];
    // data for iter0
    float4 avA0 = __ldcs(&eav[eA0 * 4 + q]);
    float4 avB0 = __ldcs(&eav[(eA0 + HALF_EDGES) * 4 + q]);
    h4 gaA0 = g_h1[sA0 * 4 + q], gbA0 = g_h2[dA0 * 4 + q];
    h4 gaB0 = g_h1[sB0 * 4 + q], gbB0 = g_h2[dB0 * 4 + q];

    #pragma unroll 1
    for (int it = 0; it < ES_ITERS; it++) {
        // stage B: data loads for iter+1 (indices arrived a full body ago)
        float4 avA1n, avB1n;
        h4 gaA1n, gbA1n, gaB1n, gbB1n;
        if (it + 1 < ES_ITERS) {
            avA1n = __ldcs(&eav[eA1 * 4 + q]);
            avB1n = __ldcs(&eav[(eA1 + HALF_EDGES) * 4 + q]);
            gaA1n = g_h1[sA1 * 4 + q]; gbA1n = g_h2[dA1 * 4 + q];
            gaB1n = g_h1[sB1 * 4 + q]; gbB1n = g_h2[dB1 * 4 + q];
        }
        // stage A: index loads for iter+2
        int eA2 = eA1 + NQUADS;
        int sA2 = 0, dA2 = 0, sB2 = 0, dB2 = 0;
        if (it + 2 < ES_ITERS) {
            sA2 = ei[eA2];              dA2 = ei[NEDGES + eA2];
            sB2 = ei[eA2 + HALF_EDGES]; dB2 = ei[NEDGES + eA2 + HALF_EDGES];
        }

        // stage C: compute both edges (independent chains, interleaved)
        float accA[4] = {0.f, 0.f, 0.f, 0.f};
        float accB[4] = {0.f, 0.f, 0.f, 0.f};
        #pragma unroll
        for (int g = 0; g < 4; g++) {
            int src = qbase | g;
            float xa0 = __shfl_sync(0xffffffffu, avA0.x, src);
            float xa1 = __shfl_sync(0xffffffffu, avA0.y, src);
            float xa2 = __shfl_sync(0xffffffffu, avA0.z, src);
            float xa3 = __shfl_sync(0xffffffffu, avA0.w, src);
            float xb0 = __shfl_sync(0xffffffffu, avB0.x, src);
            float xb1 = __shfl_sync(0xffffffffu, avB0.y, src);
            float xb2 = __shfl_sync(0xffffffffu, avB0.z, src);
            float xb3 = __shfl_sync(0xffffffffu, avB0.w, src);
            #pragma unroll
            for (int i = 0; i < 4; i++) {
                accA[i] = fmaf(xa0, w[i][g].x, accA[i]);
                accB[i] = fmaf(xb0, w[i][g].x, accB[i]);
                accA[i] = fmaf(xa1, w[i][g].y, accA[i]);
                accB[i] = fmaf(xb1, w[i][g].y, accB[i]);
                accA[i] = fmaf(xa2, w[i][g].z, accA[i]);
                accB[i] = fmaf(xb2, w[i][g].z, accB[i]);
                accA[i] = fmaf(xa3, w[i][g].w, accA[i]);
                accB[i] = fmaf(xb3, w[i][g].w, accB[i]);
            }
        }
        {
            __half2 hA01 = __hadd2(gaA0.a, gbA0.a);
            __half2 hA23 = __hadd2(gaA0.b, gbA0.b);
            __half2 hB01 = __hadd2(gaB0.a, gbB0.a);
            __half2 hB23 = __hadd2(gaB0.b, gbB0.b);
            float2 fA01 = __half22float2(hA01), fA23 = __half22float2(hA23);
            float2 fB01 = __half22float2(hB01), fB23 = __half22float2(hB23);
            accA[0] += fA01.x; accA[1] += fA01.y; accA[2] += fA23.x; accA[3] += fA23.y;
            accB[0] += fB01.x; accB[1] += fB01.y; accB[2] += fB23.x; accB[3] += fB23.y;
        }

        // fp32 stats (pre-rounding), both edges
        #pragma unroll
        for (int i = 0; i < 4; i++) {
            S[i] += accA[i] + accB[i];
            Q[i] = fmaf(accA[i], accA[i], Q[i]);
            Q[i] = fmaf(accB[i], accB[i], Q[i]);
        }
        // fp16 e to scratch (8 B/thread each, lane-consecutive, streaming)
        union { h4 h; float2 f; } hvA, hvB;
        hvA.h.a = __floats2half2_rn(accA[0], accA[1]);
        hvA.h.b = __floats2half2_rn(accA[2], accA[3]);
        hvB.h.a = __floats2half2_rn(accB[0], accB[1]);
        hvB.h.b = __floats2half2_rn(accB[2], accB[3]);
        __stcs(&ev[eA0 * 4 + q], hvA.f);
        __stcs(&ev[(eA0 + HALF_EDGES) * 4 + q], hvB.f);

        // rotate pipeline
        eA0 = eA1;
        avA0 = avA1n; gaA0 = gaA1n; gbA0 = gbA1n;
        avB0 = avB1n; gaB0 = gaB1n; gbB0 = gbB1n;
        eA1 = eA2;
        sA1 = sA2; dA1 = dA2; sB1 = sB2; dB1 = dB2;
    }

    // Reduce across lanes with same q (offsets 4,8,16): lanes 0..3 hold totals
    #pragma unroll
    for (int i = 0; i < 4; i++) {
        #pragma unroll
        for (int o = 4; o < 32; o <<= 1) {
            S[i] += __shfl_xor_sync(0xffffffffu, S[i], o);
            Q[i] += __shfl_xor_sync(0xffffffffu, Q[i], o);
        }
    }
    int wrp = tid >> 5;
    if (lane < 4) {
        #pragma unroll
        for (int i = 0; i < 4; i++) {
            red[wrp][lane * 4 + i] = S[i];       // feature j = 4*lane + i
            red[wrp][16 + lane * 4 + i] = Q[i];
        }
    }
    __syncthreads();
    if (tid < 32) {
        float acc = 0.f;
        #pragma unroll
        for (int w2 = 0; w2 < 8; w2++) acc += red[w2][tid];
        atomicAdd(&g_accum[tid], acc);
    }
}

// ============================================================================
// Kernel 3: finalize BN affine
// ============================================================================
__global__ void bn_finalize(const float* __restrict__ gamma,
                            const float* __restrict__ beta) {
    int j = threadIdx.x;
    if (j < 16) {
        float inv_n = 1.0f / (float)NEDGES;
        float mean = g_accum[j] * inv_n;
        float var = g_accum[16 + j] * inv_n - mean * mean;
        float sc = gamma[j] * rsqrtf(var + 1e-5f);
        g_scale[j] = sc;
        g_shift[j] = beta[j] - mean * sc;
    }
}

// ============================================================================
// Kernel 4: pass 2 — pure streaming: out = ea + relu(e*scale + shift).
// One float4 (= one (edge, quarter) slice) per thread. At DRAM roofline.
// Also the clock-variance control: code and data identical across rounds.
// ============================================================================
__global__ void __launch_bounds__(256) edge_apply(const float* __restrict__ ea,
                                                  float* __restrict__ out) {
    int idx = blockIdx.x * blockDim.x + threadIdx.x;   // 0 .. NEDGES*4-1
    int q = idx & 3;
    float4 sc = ((const float4*)g_scale)[q];           // broadcast, L1-hit
    float4 sh = ((const float4*)g_shift)[q];

    float4 av = ((const float4*)ea)[idx];
    h4 v = ((const h4*)g_e)[idx];
    float2 f01 = __half22float2(v.a);
    float2 f23 = __half22float2(v.b);

    float4 o;
    o.x = av.x + fmaxf(fmaf(f01.x, sc.x, sh.x), 0.f);
    o.y = av.y + fmaxf(fmaf(f01.y, sc.y, sh.y), 0.f);
    o.z = av.z + fmaxf(fmaf(f23.x, sc.z, sh.z), 0.f);
    o.w = av.w + fmaxf(fmaf(f23.y, sc.w, sh.w), 0.f);
    ((float4*)out)[idx] = o;
}

extern "C" void kernel_launch(void* const* d_in, const int* in_sizes, int n_in,
                              void* d_out, int out_size) {
    (void)in_sizes; (void)n_in; (void)out_size;
    const float* x     = (const float*)d_in[0];
    const int*   ei    = (const int*)d_in[1];     // int32 on device (JAX x64 off)
    const float* ea    = (const float*)d_in[2];
    const float* W0    = (const float*)d_in[3];
    const float* b0    = (const float*)d_in[4];
    const float* W1    = (const float*)d_in[5];
    const float* b1    = (const float*)d_in[6];
    const float* W2    = (const float*)d_in[7];
    const float* b2    = (const float*)d_in[8];
    const float* gamma = (const float*)d_in[9];
    const float* beta  = (const float*)d_in[10];
    float* out = (float*)d_out;

    node_prep<<<(NNODES + 255) / 256, 256>>>(x, W1, W2, b0, b1, b2);
    edge_stats<<<ES_BLOCKS, ES_THREADS>>>(ea, ei, W0);  // 10 iters × 2 edges/quad
    bn_finalize<<<1, 32>>>(gamma, beta);
    edge_apply<<<(NEDGES * 4) / 256, 256>>>(ea, out);   // 50000 blocks, 1 float4/thread
}